// round 2
// baseline (speedup 1.0000x reference)
#include <cuda_runtime.h>

// Problem constants
#define HH 14
#define WWD 14
#define HW 196
#define CH 512
#define NCHAIN 8     // 4 modes x 2 batches
#define CLUS 8       // CTAs per cluster (one chain)
#define NTHR 512

// Static device scratch (no allocations allowed)
__device__ float g_A0[2 * HW * CH];           // Wx@input + b_in, [b][pixel][c]
__device__ float g_G [NCHAIN * HW * CH];      // cached Wh@h_vi per cell
__device__ float g_Hv[NCHAIN * HW * CH];      // h_vi history for epilogue
__device__ float g_Part[NCHAIN * CLUS * CH];  // per-CTA partial h_vi
__device__ float g_Y[2 * HW * CH];            // pre-softmax logits [b][p][c]

__device__ __forceinline__ float4 relu4(float4 a) {
    return make_float4(fmaxf(a.x, 0.f), fmaxf(a.y, 0.f),
                       fmaxf(a.z, 0.f), fmaxf(a.w, 0.f));
}
__device__ __forceinline__ float4 add4(float4 a, float4 b) {
    return make_float4(a.x + b.x, a.y + b.y, a.z + b.z, a.w + b.w);
}
__device__ __forceinline__ float max4(float4 a) {
    return fmaxf(fmaxf(a.x, a.y), fmaxf(a.z, a.w));
}
__device__ __forceinline__ float sum4(float4 a) {
    return (a.x + a.y) + (a.z + a.w);
}
__device__ __forceinline__ float4 exp4(float4 a, float m) {
    return make_float4(__expf(a.x - m), __expf(a.y - m),
                       __expf(a.z - m), __expf(a.w - m));
}

#define CLUSTER_ARRIVE() asm volatile("barrier.cluster.arrive.aligned;" ::: "memory")
#define CLUSTER_WAIT()   asm volatile("barrier.cluster.wait.aligned;" ::: "memory")

// ---------------------------------------------------------------------------
// Prologue: A0[b][p][c] = sum_k Wx[c,k]*input[b,k,p] + b_in[c]
// grid 98 blocks (2 batches x 49 tiles of 4 pixels), 512 threads = out channel
// ---------------------------------------------------------------------------
__global__ __launch_bounds__(NTHR) void prologue_kernel(
    const float* __restrict__ input, const float* __restrict__ Wx,
    const float* __restrict__ b_in) {
    __shared__ float xs[4 * 520];   // [j][k], padded stride
    const int tid = threadIdx.x;
    const int b   = blockIdx.x / 49;
    const int p0  = (blockIdx.x % 49) * 4;
#pragma unroll
    for (int j = 0; j < 4; j++)
        xs[j * 520 + tid] = input[(size_t)(b * CH + tid) * HW + p0 + j];
    __syncthreads();
    const float4* w4 = (const float4*)(Wx + (size_t)tid * CH);
    float acc[4] = {0.f, 0.f, 0.f, 0.f};
    for (int k4 = 0; k4 < CH / 4; k4++) {
        float4 w = w4[k4];
#pragma unroll
        for (int j = 0; j < 4; j++) {
            float4 x = *(const float4*)(xs + j * 520 + 4 * k4);
            acc[j] += w.x * x.x + w.y * x.y + w.z * x.z + w.w * x.w;
        }
    }
    float bb = b_in[tid];
#pragma unroll
    for (int j = 0; j < 4; j++)
        g_A0[(size_t)(b * HW + p0 + j) * CH + tid] = acc[j] + bb;
}

// ---------------------------------------------------------------------------
// Scan: one 8-CTA cluster per chain, 196 sequential steps.
// Per step: cells->warps softmax-pool, CTA reduce, cluster reduce (barrier1),
// register-resident Wh matvec -> G[p], barrier2.
// ---------------------------------------------------------------------------
__global__ void __cluster_dims__(CLUS, 1, 1) __launch_bounds__(NTHR, 1)
scan_kernel(const float* __restrict__ Wh) {
    __shared__ float slab[16 * CH];   // per-warp partial h_vi
    __shared__ float hvi[CH];         // reduced h_vi

    const int tid   = threadIdx.x;
    const int wid   = tid >> 5, lane = tid & 31;
    const int chain = blockIdx.x / CLUS;
    const int rank  = blockIdx.x % CLUS;
    const int mode  = chain >> 1;
    const int bb    = chain & 1;
    const int lr    = tid >> 3, seg = tid & 7;   // matvec row-in-slice, k-segment
    const int rowg  = rank * 64 + lr;            // global Wh row for this thread

    // This CTA's 64x512 slice of Wh -> registers.
    // Thread covers k4 in [seg*16, seg*16+16), rotated by seg for bank-free hvi reads.
    float4 wreg[16];
    {
        const float4* Wh4 = (const float4*)Wh;
#pragma unroll
        for (int j = 0; j < 16; j++) {
            int k4 = seg * 16 + ((j + seg) & 15);
            wreg[j] = Wh4[(size_t)rowg * 128 + k4];
        }
    }

    float* Gc = g_G  + (size_t)chain * HW * CH;
    float* Hc = g_Hv + (size_t)chain * HW * CH;
    float* Pc = g_Part + (size_t)chain * CLUS * CH;
    const float* Ab = g_A0 + (size_t)bb * HW * CH;

    const int gw = rank * 16 + wid;   // cluster-wide warp id (0..127)
    float4* myslab = (float4*)(slab + wid * CH);

    for (int p = 0; p < HW; p++) {
        const int px = p / WWD, py = p - px * WWD;
        const int fx = (mode & 2) ? (HH - 1 - px) : px;
        const int fy = (mode & 1) ? (WWD - 1 - py) : py;
        const float4* a4 = (const float4*)(Ab + (size_t)(fx * WWD + fy) * CH);
        float4 a0 = __ldg(a4 + lane),      a1 = __ldg(a4 + lane + 32);
        float4 a2 = __ldg(a4 + lane + 64), a3 = __ldg(a4 + lane + 96);

        const int pw = py + 1;
        const int wcount = (px + 1) * pw;

        bool first = true;
        for (int ci = gw; ci < wcount; ci += CLUS * 16) {
            int cx = ci / pw;
            int cell = cx * WWD + (ci - cx * pw);
            float4 z0, z1, z2, z3;
            if (cell == p) {   // current cell: h == 0 -> G == 0
                z0 = relu4(a0); z1 = relu4(a1); z2 = relu4(a2); z3 = relu4(a3);
            } else {
                const float4* g4 = (const float4*)(Gc + (size_t)cell * CH);
                float4 v0 = __ldcg(g4 + lane),      v1 = __ldcg(g4 + lane + 32);
                float4 v2 = __ldcg(g4 + lane + 64), v3 = __ldcg(g4 + lane + 96);
                z0 = relu4(add4(a0, v0)); z1 = relu4(add4(a1, v1));
                z2 = relu4(add4(a2, v2)); z3 = relu4(add4(a3, v3));
            }
            // per-cell softmax over all 512 channels (whole warp = one cell)
            float m = fmaxf(fmaxf(max4(z0), max4(z1)), fmaxf(max4(z2), max4(z3)));
#pragma unroll
            for (int o = 16; o; o >>= 1)
                m = fmaxf(m, __shfl_xor_sync(0xffffffffu, m, o));
            float4 e0 = exp4(z0, m), e1 = exp4(z1, m);
            float4 e2 = exp4(z2, m), e3 = exp4(z3, m);
            float es = sum4(e0) + sum4(e1) + sum4(e2) + sum4(e3);
#pragma unroll
            for (int o = 16; o; o >>= 1)
                es += __shfl_xor_sync(0xffffffffu, es, o);
            float inv = __fdividef(1.f, es);
            float4 c0 = make_float4(z0.x * e0.x * inv, z0.y * e0.y * inv, z0.z * e0.z * inv, z0.w * e0.w * inv);
            float4 c1 = make_float4(z1.x * e1.x * inv, z1.y * e1.y * inv, z1.z * e1.z * inv, z1.w * e1.w * inv);
            float4 c2 = make_float4(z2.x * e2.x * inv, z2.y * e2.y * inv, z2.z * e2.z * inv, z2.w * e2.w * inv);
            float4 c3 = make_float4(z3.x * e3.x * inv, z3.y * e3.y * inv, z3.z * e3.z * inv, z3.w * e3.w * inv);
            if (first) {
                myslab[lane] = c0; myslab[lane + 32] = c1;
                myslab[lane + 64] = c2; myslab[lane + 96] = c3;
            } else {
                myslab[lane]      = add4(myslab[lane], c0);
                myslab[lane + 32] = add4(myslab[lane + 32], c1);
                myslab[lane + 64] = add4(myslab[lane + 64], c2);
                myslab[lane + 96] = add4(myslab[lane + 96], c3);
            }
            first = false;
        }
        __syncthreads();

        // CTA reduce over warps that actually had cells
        int nwl = wcount - rank * 16;
        nwl = nwl < 0 ? 0 : (nwl > 16 ? 16 : nwl);
        float s = 0.f;
        for (int w = 0; w < nwl; w++) s += slab[w * CH + tid];
        Pc[rank * CH + tid] = s;             // ordered by release on cluster.arrive

        CLUSTER_ARRIVE();                    // barrier1 (release)
        CLUSTER_WAIT();                      //          (acquire)

        // cluster reduce -> full h_vi
        float h = 0.f;
#pragma unroll
        for (int r = 0; r < CLUS; r++) h += __ldcg(Pc + r * CH + tid);
        hvi[tid] = h;
        Hc[(size_t)p * CH + tid] = h;        // history for epilogue
        __syncthreads();

        // matvec: G[p][rowg] = Wh[rowg,:] . hvi  (Wh slice in registers)
        const float4* hv4 = (const float4*)hvi;
        float acc = 0.f;
#pragma unroll
        for (int j = 0; j < 16; j++) {
            int k4 = seg * 16 + ((j + seg) & 15);
            float4 hh = hv4[k4];
            float4 w  = wreg[j];
            acc += w.x * hh.x + w.y * hh.y + w.z * hh.z + w.w * hh.w;
        }
        acc += __shfl_xor_sync(0xffffffffu, acc, 1);
        acc += __shfl_xor_sync(0xffffffffu, acc, 2);
        acc += __shfl_xor_sync(0xffffffffu, acc, 4);
        if (seg == 0) Gc[(size_t)p * CH + rowg] = acc;

        CLUSTER_ARRIVE();                    // barrier2: G[p] visible before next step
        CLUSTER_WAIT();
        __syncthreads();                     // slab reuse safety
    }
}

// ---------------------------------------------------------------------------
// Epilogue GEMM: Y[b][p][c] = sum_k Wo[c,k] * (sum_m Hv[m*2+b][p][k]) + 4*b_out[c]
// ---------------------------------------------------------------------------
__global__ __launch_bounds__(NTHR) void epilogue_kernel(
    const float* __restrict__ Wo, const float* __restrict__ b_out) {
    __shared__ float hs[4 * 520];   // [j][k]
    const int tid = threadIdx.x;
    const int b   = blockIdx.x / 49;
    const int p0  = (blockIdx.x % 49) * 4;
#pragma unroll
    for (int j = 0; j < 4; j++) {
        float s = 0.f;
#pragma unroll
        for (int m = 0; m < 4; m++)
            s += g_Hv[((size_t)(m * 2 + b) * HW + p0 + j) * CH + tid];
        hs[j * 520 + tid] = s;
    }
    __syncthreads();
    const float4* w4 = (const float4*)(Wo + (size_t)tid * CH);
    float acc[4] = {0.f, 0.f, 0.f, 0.f};
    for (int k4 = 0; k4 < CH / 4; k4++) {
        float4 w = w4[k4];
#pragma unroll
        for (int j = 0; j < 4; j++) {
            float4 h = *(const float4*)(hs + j * 520 + 4 * k4);
            acc[j] += w.x * h.x + w.y * h.y + w.z * h.z + w.w * h.w;
        }
    }
    float bo = 4.f * b_out[tid];
#pragma unroll
    for (int j = 0; j < 4; j++)
        g_Y[(size_t)(b * HW + p0 + j) * CH + tid] = acc[j] + bo;
}

// ---------------------------------------------------------------------------
// Final channel softmax: out[b][c][p] = softmax_c(Y[b][p][c])
// grid 392 (one per b,p), 128 threads x float4
// ---------------------------------------------------------------------------
__global__ __launch_bounds__(128) void softmax_kernel(float* __restrict__ out) {
    __shared__ float red[4];
    const int bp = blockIdx.x;
    const int b = bp / HW, p = bp % HW;
    const int t = threadIdx.x, w = t >> 5, ln = t & 31;
    const float4* y4 = (const float4*)(g_Y + (size_t)bp * CH);
    float4 v = y4[t];
    float m = max4(v);
#pragma unroll
    for (int o = 16; o; o >>= 1) m = fmaxf(m, __shfl_xor_sync(0xffffffffu, m, o));
    if (ln == 0) red[w] = m;
    __syncthreads();
    m = fmaxf(fmaxf(red[0], red[1]), fmaxf(red[2], red[3]));
    __syncthreads();
    float4 e = exp4(v, m);
    float s = sum4(e);
#pragma unroll
    for (int o = 16; o; o >>= 1) s += __shfl_xor_sync(0xffffffffu, s, o);
    if (ln == 0) red[w] = s;
    __syncthreads();
    s = red[0] + red[1] + red[2] + red[3];
    float inv = 1.f / s;
    float* o = out + (size_t)b * CH * HW + p;
    int c = 4 * t;
    o[(size_t)(c + 0) * HW] = e.x * inv;
    o[(size_t)(c + 1) * HW] = e.y * inv;
    o[(size_t)(c + 2) * HW] = e.z * inv;
    o[(size_t)(c + 3) * HW] = e.w * inv;
}

extern "C" void kernel_launch(void* const* d_in, const int* in_sizes, int n_in,
                              void* d_out, int out_size) {
    const float* input = (const float*)d_in[0];
    const float* Wx    = (const float*)d_in[1];
    const float* Wh    = (const float*)d_in[2];
    const float* b_in  = (const float*)d_in[3];
    const float* Wo    = (const float*)d_in[4];
    const float* b_out = (const float*)d_in[5];
    float* out = (float*)d_out;
    (void)in_sizes; (void)n_in; (void)out_size;

    prologue_kernel<<<98, NTHR>>>(input, Wx, b_in);
    scan_kernel<<<NCHAIN * CLUS, NTHR>>>(Wh);
    epilogue_kernel<<<98, NTHR>>>(Wo, b_out);
    softmax_kernel<<<2 * HW, 128>>>(out);
}

// round 5
// speedup vs baseline: 1.1604x; 1.1604x over previous
#include <cuda_runtime.h>
#include <cstdint>

// Problem constants
#define HH 14
#define WWD 14
#define HW 196
#define CH 512
#define NCHAIN 8     // 4 modes x 2 batches
#define CLUS 8       // CTAs per cluster (one chain)
#define NTHR 512

// Dynamic smem layout (bytes)
#define OFF_GHIST 0
#define OFF_SLAB  (OFF_GHIST + 32 * CH * 4)   // 65536
#define OFF_HVI   (OFF_SLAB + 16 * CH * 4)    // 98304
#define OFF_ASMEM (OFF_HVI + CH * 4)          // 100352
#define SMEM_SZ   (OFF_ASMEM + 2 * CH * 4)    // 104448

// Static device scratch
__device__ float g_A0[2 * HW * CH];               // Wx@input + b_in, [b][pixel][c]
__device__ float g_Hv[NCHAIN * HW * CH];          // h_vi history for epilogue
__device__ float g_Part[NCHAIN * 2 * CLUS * CH];  // per-CTA partial h_vi, double buffered
__device__ float g_Y[2 * HW * CH];                // pre-softmax logits

__device__ __forceinline__ float4 relu4(float4 a) {
    return make_float4(fmaxf(a.x, 0.f), fmaxf(a.y, 0.f),
                       fmaxf(a.z, 0.f), fmaxf(a.w, 0.f));
}
__device__ __forceinline__ float4 add4(float4 a, float4 b) {
    return make_float4(a.x + b.x, a.y + b.y, a.z + b.z, a.w + b.w);
}
__device__ __forceinline__ float max4(float4 a) {
    return fmaxf(fmaxf(a.x, a.y), fmaxf(a.z, a.w));
}
__device__ __forceinline__ float sum4(float4 a) {
    return (a.x + a.y) + (a.z + a.w);
}
__device__ __forceinline__ float4 exp4(float4 a, float m) {
    return make_float4(__expf(a.x - m), __expf(a.y - m),
                       __expf(a.z - m), __expf(a.w - m));
}
__device__ __forceinline__ float warp_max(float v) {
#pragma unroll
    for (int o = 16; o; o >>= 1)
        v = fmaxf(v, __shfl_xor_sync(0xffffffffu, v, o));
    return v;
}
__device__ __forceinline__ uint32_t s2u(const void* p) {
    uint32_t a;
    asm("{ .reg .u64 t; cvta.to.shared.u64 t, %1; cvt.u32.u64 %0, t; }"
        : "=r"(a) : "l"(p));
    return a;
}
__device__ __forceinline__ void st_cluster_f32(uint32_t laddr, uint32_t rnk, float v) {
    uint32_t ra;
    asm("mapa.shared::cluster.u32 %0, %1, %2;" : "=r"(ra) : "r"(laddr), "r"(rnk));
    asm volatile("st.shared::cluster.f32 [%0], %1;" :: "r"(ra), "f"(v) : "memory");
}
// HW cluster barrier, split form. arrive = release, wait = acquire (cluster scope).
#define CLUSTER_ARRIVE() asm volatile("barrier.cluster.arrive.aligned;" ::: "memory")
#define CLUSTER_WAIT()   asm volatile("barrier.cluster.wait.aligned;"   ::: "memory")

struct C4 { float4 v0, v1, v2, v3; };

// Per-cell softmax-pool contribution. Whole warp = one cell (512 ch, 16/lane).
__device__ __forceinline__ C4 cell_contrib(int cell, int p, const float* ghist,
                                           const float4* aps, int lane) {
    float4 z0, z1, z2, z3;
    if (cell == p) {   // current cell: h == 0 -> G == 0
        z0 = relu4(aps[lane]);      z1 = relu4(aps[lane + 32]);
        z2 = relu4(aps[lane + 64]); z3 = relu4(aps[lane + 96]);
    } else {
        int slot = (cell & 15) + ((cell >> 7) << 4);
        const float4* g4 = (const float4*)(ghist + slot * CH);
        z0 = relu4(add4(aps[lane],      g4[lane]));
        z1 = relu4(add4(aps[lane + 32], g4[lane + 32]));
        z2 = relu4(add4(aps[lane + 64], g4[lane + 64]));
        z3 = relu4(add4(aps[lane + 96], g4[lane + 96]));
    }
    float m = fmaxf(fmaxf(max4(z0), max4(z1)), fmaxf(max4(z2), max4(z3)));
    m = warp_max(m);
    float4 e0 = exp4(z0, m), e1 = exp4(z1, m);
    float4 e2 = exp4(z2, m), e3 = exp4(z3, m);
    float es = sum4(e0) + sum4(e1) + sum4(e2) + sum4(e3);
#pragma unroll
    for (int o = 16; o; o >>= 1)
        es += __shfl_xor_sync(0xffffffffu, es, o);
    float inv = __fdividef(1.f, es);
    C4 r;
    r.v0 = make_float4(z0.x * e0.x * inv, z0.y * e0.y * inv, z0.z * e0.z * inv, z0.w * e0.w * inv);
    r.v1 = make_float4(z1.x * e1.x * inv, z1.y * e1.y * inv, z1.z * e1.z * inv, z1.w * e1.w * inv);
    r.v2 = make_float4(z2.x * e2.x * inv, z2.y * e2.y * inv, z2.z * e2.z * inv, z2.w * e2.w * inv);
    r.v3 = make_float4(z3.x * e3.x * inv, z3.y * e3.y * inv, z3.z * e3.z * inv, z3.w * e3.w * inv);
    return r;
}

// ---------------------------------------------------------------------------
// Prologue: A0[b][p][c] = sum_k Wx[c,k]*input[b,k,p] + b_in[c]
// ---------------------------------------------------------------------------
__global__ __launch_bounds__(NTHR) void prologue_kernel(
    const float* __restrict__ input, const float* __restrict__ Wx,
    const float* __restrict__ b_in) {
    __shared__ float xs[4 * 520];
    const int tid = threadIdx.x;
    const int b   = blockIdx.x / 49;
    const int p0  = (blockIdx.x % 49) * 4;
#pragma unroll
    for (int j = 0; j < 4; j++)
        xs[j * 520 + tid] = input[(size_t)(b * CH + tid) * HW + p0 + j];
    __syncthreads();
    const float4* w4 = (const float4*)(Wx + (size_t)tid * CH);
    float acc[4] = {0.f, 0.f, 0.f, 0.f};
    for (int k4 = 0; k4 < CH / 4; k4++) {
        float4 w = w4[k4];
#pragma unroll
        for (int j = 0; j < 4; j++) {
            float4 x = *(const float4*)(xs + j * 520 + 4 * k4);
            acc[j] += w.x * x.x + w.y * x.y + w.z * x.z + w.w * x.w;
        }
    }
    float bb = b_in[tid];
#pragma unroll
    for (int j = 0; j < 4; j++)
        g_A0[(size_t)(b * HW + p0 + j) * CH + tid] = acc[j] + bb;
}

// ---------------------------------------------------------------------------
// Scan: one 8-CTA cluster per chain, 196 sequential steps.
// G history lives in the OWNER CTA's smem (cells assigned by id%128 -> warp).
// Split cluster-barrier generations: B1 = partials ready, B2 = scatter ready.
// B2's wait is deferred past the bulk of next step's window pass.
// ---------------------------------------------------------------------------
__global__ void __cluster_dims__(CLUS, 1, 1) __launch_bounds__(NTHR, 1)
scan_kernel(const float* __restrict__ Wh) {
    extern __shared__ char smem[];
    const uint32_t sbase = s2u(smem);
    float* ghist = (float*)(smem + OFF_GHIST);
    float* slab  = (float*)(smem + OFF_SLAB);
    float* hvi   = (float*)(smem + OFF_HVI);
    float* asmem = (float*)(smem + OFF_ASMEM);   // ping-pong a buffers

    const int tid  = threadIdx.x;
    const int wid  = tid >> 5, lane = tid & 31;
    const int rank = blockIdx.x & 7;             // == cluster_ctarank (1-D cluster)
    const int chain = blockIdx.x >> 3;
    const int mode = chain >> 1, bb = chain & 1;
    const int lr = tid >> 3, seg = tid & 7;
    const int rowg = rank * 64 + lr;
    const int gw = rank * 16 + wid;              // cluster-wide warp id 0..127
    const int c1 = gw, c2 = gw + 128;
    const int cx1 = c1 / WWD, cy1 = c1 - cx1 * WWD;
    const int cx2 = c2 / WWD, cy2 = c2 - cx2 * WWD;
    const bool has2 = (c2 < HW);

    // This CTA's 64x512 slice of Wh -> registers (bank-rotated k layout)
    float4 wreg[16];
    {
        const float4* Wh4 = (const float4*)Wh;
#pragma unroll
        for (int j = 0; j < 16; j++) {
            int k4 = seg * 16 + ((j + seg) & 15);
            wreg[j] = Wh4[(size_t)rowg * 128 + k4];
        }
    }

    const float* Ab = g_A0 + (size_t)bb * HW * CH;
    float* Pc0 = g_Part + (size_t)chain * 2 * CLUS * CH;
    float* Hc  = g_Hv + (size_t)chain * HW * CH;

    // a(p=0) -> asmem buf 0 (1 float per thread)
    {
        int fx = (mode & 2) ? (HH - 1) : 0;
        int fy = (mode & 1) ? (WWD - 1) : 0;
        asmem[tid] = __ldg(Ab + (size_t)(fx * WWD + fy) * CH + tid);
    }
    __syncthreads();

    float4* myslab = (float4*)(slab + wid * CH);

    for (int p = 0; p < HW; p++) {
        const int px = p / WWD, py = p - px * WWD;
        const float4* aps = (const float4*)(asmem + (p & 1) * CH);

        const bool act1 = (cx1 <= px) && (cy1 <= py);
        const bool act2 = has2 && (cx2 <= px) && (cy2 <= py);
        const bool d1 = act1 && (c1 == p - 1);   // cell p-1 needs this step's B2 wait
        const bool d2 = act2 && (c2 == p - 1);

        // ---- window pass, non-deferred cells (G already visible) ----
        C4 acc;
        float4 zz = make_float4(0.f, 0.f, 0.f, 0.f);
        acc.v0 = zz; acc.v1 = zz; acc.v2 = zz; acc.v3 = zz;
        bool any = false;
        if (act1 && !d1) { acc = cell_contrib(c1, p, ghist, aps, lane); any = true; }
        if (act2 && !d2) {
            C4 r = cell_contrib(c2, p, ghist, aps, lane);
            if (any) {
                acc.v0 = add4(acc.v0, r.v0); acc.v1 = add4(acc.v1, r.v1);
                acc.v2 = add4(acc.v2, r.v2); acc.v3 = add4(acc.v3, r.v3);
            } else acc = r;
            any = true;
        }

        if (p > 0) CLUSTER_WAIT();               // B2(p-1): scatter of cell p-1 visible

        if (d1 | d2) {
            C4 r = cell_contrib(d1 ? c1 : c2, p, ghist, aps, lane);
            if (any) {
                acc.v0 = add4(acc.v0, r.v0); acc.v1 = add4(acc.v1, r.v1);
                acc.v2 = add4(acc.v2, r.v2); acc.v3 = add4(acc.v3, r.v3);
            } else acc = r;
        }
        myslab[lane] = acc.v0; myslab[lane + 32] = acc.v1;
        myslab[lane + 64] = acc.v2; myslab[lane + 96] = acc.v3;
        __syncthreads();                         // slab ready

        // ---- CTA reduce -> partial, publish to L2 ----
        float part = 0.f;
#pragma unroll
        for (int w = 0; w < 16; w++) part += slab[w * CH + tid];
        float* Pb = Pc0 + (p & 1) * (CLUS * CH);
        Pb[rank * CH + tid] = part;
        CLUSTER_ARRIVE();                        // B1 arrive (releases Pb store)

        // prefetch a(p+1) into the other buffer (hides behind B1 wait)
        if (p + 1 < HW) {
            int pn = p + 1, pxn = pn / WWD, pyn = pn - pxn * WWD;
            int fx = (mode & 2) ? (HH - 1 - pxn) : pxn;
            int fy = (mode & 1) ? (WWD - 1 - pyn) : pyn;
            asmem[((p + 1) & 1) * CH + tid] =
                __ldg(Ab + (size_t)(fx * WWD + fy) * CH + tid);
        }
        CLUSTER_WAIT();                          // B1 wait (acquires all Pb stores)

        // ---- cluster reduce -> full h ----
        float h = 0.f;
#pragma unroll
        for (int r = 0; r < 8; r++) h += __ldcg(Pb + r * CH + tid);
        hvi[tid] = h;
        if (rank == (p & 7)) Hc[(size_t)p * CH + tid] = h;  // history for epilogue
        __syncthreads();                         // hvi ready

        // ---- matvec: G[p][rowg] = Wh[rowg,:] . h ----
        const float4* hv4 = (const float4*)hvi;
        float q0 = 0.f, q1 = 0.f, q2 = 0.f, q3 = 0.f;
#pragma unroll
        for (int j = 0; j < 16; j += 4) {
            { int k4 = seg * 16 + ((j + 0 + seg) & 15); float4 hh = hv4[k4], w = wreg[j + 0];
              q0 += w.x * hh.x + w.y * hh.y + w.z * hh.z + w.w * hh.w; }
            { int k4 = seg * 16 + ((j + 1 + seg) & 15); float4 hh = hv4[k4], w = wreg[j + 1];
              q1 += w.x * hh.x + w.y * hh.y + w.z * hh.z + w.w * hh.w; }
            { int k4 = seg * 16 + ((j + 2 + seg) & 15); float4 hh = hv4[k4], w = wreg[j + 2];
              q2 += w.x * hh.x + w.y * hh.y + w.z * hh.z + w.w * hh.w; }
            { int k4 = seg * 16 + ((j + 3 + seg) & 15); float4 hh = hv4[k4], w = wreg[j + 3];
              q3 += w.x * hh.x + w.y * hh.y + w.z * hh.z + w.w * hh.w; }
        }
        float accv = (q0 + q1) + (q2 + q3);
        accv += __shfl_xor_sync(0xffffffffu, accv, 1);
        accv += __shfl_xor_sync(0xffffffffu, accv, 2);
        accv += __shfl_xor_sync(0xffffffffu, accv, 4);

        // ---- scatter this CTA's 64 G values into owner's ghist slot ----
        if (seg == 0) {
            const uint32_t orank = (uint32_t)((p & 127) >> 4);
            int slot = (p & 15) + ((p >> 7) << 4);
            uint32_t laddr = sbase + OFF_GHIST +
                             (uint32_t)((slot * CH + rank * 64 + lr) * 4);
            st_cluster_f32(laddr, orank, accv);
        }
        CLUSTER_ARRIVE();                        // B2 arrive (releases scatter)
    }
    CLUSTER_WAIT();                              // close last B2 generation
}

// ---------------------------------------------------------------------------
// Epilogue GEMM: Y[b][p][c] = Wo @ (sum_m Hv[m*2+b][p]) + 4*b_out
// ---------------------------------------------------------------------------
__global__ __launch_bounds__(NTHR) void epilogue_kernel(
    const float* __restrict__ Wo, const float* __restrict__ b_out) {
    __shared__ float hs[4 * 520];
    const int tid = threadIdx.x;
    const int b   = blockIdx.x / 49;
    const int p0  = (blockIdx.x % 49) * 4;
#pragma unroll
    for (int j = 0; j < 4; j++) {
        float s = 0.f;
#pragma unroll
        for (int m = 0; m < 4; m++)
            s += g_Hv[((size_t)(m * 2 + b) * HW + p0 + j) * CH + tid];
        hs[j * 520 + tid] = s;
    }
    __syncthreads();
    const float4* w4 = (const float4*)(Wo + (size_t)tid * CH);
    float acc[4] = {0.f, 0.f, 0.f, 0.f};
    for (int k4 = 0; k4 < CH / 4; k4++) {
        float4 w = w4[k4];
#pragma unroll
        for (int j = 0; j < 4; j++) {
            float4 h = *(const float4*)(hs + j * 520 + 4 * k4);
            acc[j] += w.x * h.x + w.y * h.y + w.z * h.z + w.w * h.w;
        }
    }
    float bo = 4.f * b_out[tid];
#pragma unroll
    for (int j = 0; j < 4; j++)
        g_Y[(size_t)(b * HW + p0 + j) * CH + tid] = acc[j] + bo;
}

// ---------------------------------------------------------------------------
// Final channel softmax: out[b][c][p] = softmax_c(Y[b][p][c])
// ---------------------------------------------------------------------------
__global__ __launch_bounds__(128) void softmax_kernel(float* __restrict__ out) {
    __shared__ float red[4];
    const int bp = blockIdx.x;
    const int b = bp / HW, p = bp % HW;
    const int t = threadIdx.x, w = t >> 5, ln = t & 31;
    const float4* y4 = (const float4*)(g_Y + (size_t)bp * CH);
    float4 v = y4[t];
    float m = max4(v);
    m = warp_max(m);
    if (ln == 0) red[w] = m;
    __syncthreads();
    m = fmaxf(fmaxf(red[0], red[1]), fmaxf(red[2], red[3]));
    __syncthreads();
    float4 e = exp4(v, m);
    float s = sum4(e);
#pragma unroll
    for (int o = 16; o; o >>= 1) s += __shfl_xor_sync(0xffffffffu, s, o);
    if (ln == 0) red[w] = s;
    __syncthreads();
    s = red[0] + red[1] + red[2] + red[3];
    float inv = 1.f / s;
    float* op = out + (size_t)b * CH * HW + p;
    int c = 4 * t;
    op[(size_t)(c + 0) * HW] = e.x * inv;
    op[(size_t)(c + 1) * HW] = e.y * inv;
    op[(size_t)(c + 2) * HW] = e.z * inv;
    op[(size_t)(c + 3) * HW] = e.w * inv;
}

extern "C" void kernel_launch(void* const* d_in, const int* in_sizes, int n_in,
                              void* d_out, int out_size) {
    const float* input = (const float*)d_in[0];
    const float* Wx    = (const float*)d_in[1];
    const float* Wh    = (const float*)d_in[2];
    const float* b_in  = (const float*)d_in[3];
    const float* Wo    = (const float*)d_in[4];
    const float* b_out = (const float*)d_in[5];
    float* out = (float*)d_out;
    (void)in_sizes; (void)n_in; (void)out_size;

    cudaFuncSetAttribute(scan_kernel,
                         cudaFuncAttributeMaxDynamicSharedMemorySize, SMEM_SZ);

    prologue_kernel<<<98, NTHR>>>(input, Wx, b_in);
    scan_kernel<<<NCHAIN * CLUS, NTHR, SMEM_SZ>>>(Wh);
    epilogue_kernel<<<98, NTHR>>>(Wo, b_out);
    softmax_kernel<<<2 * HW, 128>>>(out);
}